// round 1
// baseline (speedup 1.0000x reference)
#include <cuda_runtime.h>

#define NCLS 10
#define NSAMP 4
#define PER_SAMPLE 4096000          // 160*160*160
#define THREADS 256
#define BLOCKS_X 250                // 250*256 threads * 4 elem * 16 iters = 4,096,000
#define ITERS 16
#define VEC_PER_SAMPLE (PER_SAMPLE/4)   // 1,024,000 int4
#define STRIDE (BLOCKS_X*THREADS)       // 64,000 int4 per iteration

// Global scratch (no allocations allowed): [sample][3][class]  (0=pred,1=true,2=inter)
__device__ unsigned int g_counts[NSAMP * 3 * NCLS];

__global__ void zero_counts_kernel() {
    int i = threadIdx.x;
    if (i < NSAMP * 3 * NCLS) g_counts[i] = 0u;
}

__global__ __launch_bounds__(THREADS)
void hist_kernel(const int* __restrict__ yp, const int* __restrict__ yt) {
    const int sample = blockIdx.y;
    const int4* __restrict__ p4 =
        reinterpret_cast<const int4*>(yp) + (size_t)sample * VEC_PER_SAMPLE;
    const int4* __restrict__ t4 =
        reinterpret_cast<const int4*>(yt) + (size_t)sample * VEC_PER_SAMPLE;

    const int tid = blockIdx.x * THREADS + threadIdx.x;

    int accP[NCLS], accT[NCLS], accI[NCLS];
#pragma unroll
    for (int c = 0; c < NCLS; ++c) { accP[c] = 0; accT[c] = 0; accI[c] = 0; }

#pragma unroll 2
    for (int it = 0; it < ITERS; ++it) {
        const int4 p = __ldg(&p4[tid + it * STRIDE]);
        const int4 t = __ldg(&t4[tid + it * STRIDE]);
        const int pe[4] = {p.x, p.y, p.z, p.w};
        const int te[4] = {t.x, t.y, t.z, t.w};
#pragma unroll
        for (int j = 0; j < 4; ++j) {
#pragma unroll
            for (int c = 0; c < NCLS; ++c) {
                unsigned bp = __ballot_sync(0xffffffffu, pe[j] == c);
                unsigned bt = __ballot_sync(0xffffffffu, te[j] == c);
                accP[c] += __popc(bp);
                accT[c] += __popc(bt);
                accI[c] += __popc(bp & bt);   // p==c && t==c  <=>  match at class c
            }
        }
    }

    // Accumulators are warp-uniform (ballot result identical across lanes).
    __shared__ int red[THREADS / 32][3 * NCLS];
    const int warp = threadIdx.x >> 5;
    const int lane = threadIdx.x & 31;
    if (lane == 0) {
#pragma unroll
        for (int c = 0; c < NCLS; ++c) {
            red[warp][c]            = accP[c];
            red[warp][NCLS + c]     = accT[c];
            red[warp][2 * NCLS + c] = accI[c];
        }
    }
    __syncthreads();
    if (threadIdx.x < 3 * NCLS) {
        int s = 0;
#pragma unroll
        for (int w = 0; w < THREADS / 32; ++w) s += red[w][threadIdx.x];
        atomicAdd(&g_counts[sample * 3 * NCLS + threadIdx.x], (unsigned)s);
    }
}

__global__ void finalize_kernel(float* __restrict__ out) {
    if (threadIdx.x == 0 && blockIdx.x == 0) {
        float loss = 0.0f;
        for (int n = 0; n < NSAMP; ++n) {
            const unsigned* g = &g_counts[n * 3 * NCLS];
            float ctsum = 0.0f;
            for (int c = 1; c < NCLS; ++c) ctsum += (float)g[NCLS + c];
            for (int c = 1; c < NCLS; ++c) {
                const float cp = (float)g[c];
                const float ct = (float)g[NCLS + c];
                const float I  = (float)g[2 * NCLS + c];
                const float denom = cp + ct;
                if (denom > 0.0f && ctsum > 0.0f) {
                    const float dice = 2.0f * I / denom;
                    const float w = ct / ctsum / (float)NSAMP;
                    loss += w * dice;
                }
            }
        }
        out[0] = 1.0f - loss;
    }
}

extern "C" void kernel_launch(void* const* d_in, const int* in_sizes, int n_in,
                              void* d_out, int out_size) {
    const int* yp = (const int*)d_in[0];
    const int* yt = (const int*)d_in[1];
    float* out = (float*)d_out;

    zero_counts_kernel<<<1, 128>>>();
    dim3 grid(BLOCKS_X, NSAMP);
    hist_kernel<<<grid, THREADS>>>(yp, yt);
    finalize_kernel<<<1, 32>>>(out);
}

// round 2
// speedup vs baseline: 5.3151x; 5.3151x over previous
#include <cuda_runtime.h>

#define NCLS 10
#define NSAMP 4
#define PER_SAMPLE 4096000            // 160*160*160
#define THREADS 256
#define BLOCKS_X 250                  // 250*256 threads * 64 elem = 4,096,000
#define VEC_PER_SAMPLE (PER_SAMPLE/4) // 1,024,000 int4
#define STRIDE (BLOCKS_X*THREADS)     // 64,000 int4 per grid step
#define INNER 8                       // 8 int4 = 32 elements between flushes
#define OUTER 2                       // 2 * 32 = 64 elements per thread

// [sample][3][class] (0=pred,1=true,2=inter)
__device__ unsigned int g_counts[NSAMP * 3 * NCLS];

__global__ void zero_counts_kernel() {
    int i = threadIdx.x;
    if (i < NSAMP * 3 * NCLS) g_counts[i] = 0u;
}

__global__ __launch_bounds__(THREADS)
void hist_kernel(const int* __restrict__ yp, const int* __restrict__ yt) {
    const int sample = blockIdx.y;
    const int4* __restrict__ p4 =
        reinterpret_cast<const int4*>(yp) + (size_t)sample * VEC_PER_SAMPLE;
    const int4* __restrict__ t4 =
        reinterpret_cast<const int4*>(yt) + (size_t)sample * VEC_PER_SAMPLE;

    const int tid = blockIdx.x * THREADS + threadIdx.x;

    int cntP[NCLS], cntT[NCLS], cntI[NCLS];
#pragma unroll
    for (int c = 0; c < NCLS; ++c) { cntP[c] = 0; cntT[c] = 0; cntI[c] = 0; }

#pragma unroll
    for (int g = 0; g < OUTER; ++g) {
        unsigned long long aP = 0ull, aT = 0ull, aI = 0ull;
#pragma unroll
        for (int it = 0; it < INNER; ++it) {
            const int idx = tid + (g * INNER + it) * STRIDE;
            const int4 p = __ldg(&p4[idx]);
            const int4 t = __ldg(&t4[idx]);
            const int pe[4] = {p.x, p.y, p.z, p.w};
            const int te[4] = {t.x, t.y, t.z, t.w};
#pragma unroll
            for (int j = 0; j < 4; ++j) {
                const unsigned long long vp = 1ull << (6 * pe[j]);
                const unsigned long long vt = 1ull << (6 * te[j]);
                aP += vp;
                aT += vt;
                if (pe[j] == te[j]) aI += vp;
            }
        }
        // Flush: each 6-bit field holds a count <= 32
#pragma unroll
        for (int c = 0; c < NCLS; ++c) {
            cntP[c] += (int)((aP >> (6 * c)) & 63ull);
            cntT[c] += (int)((aT >> (6 * c)) & 63ull);
            cntI[c] += (int)((aI >> (6 * c)) & 63ull);
        }
    }

    // Warp reduction (REDUX.SUM), then block reduction via shared, then global atomics.
#pragma unroll
    for (int c = 0; c < NCLS; ++c) {
        cntP[c] = __reduce_add_sync(0xffffffffu, cntP[c]);
        cntT[c] = __reduce_add_sync(0xffffffffu, cntT[c]);
        cntI[c] = __reduce_add_sync(0xffffffffu, cntI[c]);
    }

    __shared__ int red[THREADS / 32][3 * NCLS];
    const int warp = threadIdx.x >> 5;
    const int lane = threadIdx.x & 31;
    if (lane == 0) {
#pragma unroll
        for (int c = 0; c < NCLS; ++c) {
            red[warp][c]            = cntP[c];
            red[warp][NCLS + c]     = cntT[c];
            red[warp][2 * NCLS + c] = cntI[c];
        }
    }
    __syncthreads();
    if (threadIdx.x < 3 * NCLS) {
        int s = 0;
#pragma unroll
        for (int w = 0; w < THREADS / 32; ++w) s += red[w][threadIdx.x];
        atomicAdd(&g_counts[sample * 3 * NCLS + threadIdx.x], (unsigned)s);
    }
}

__global__ void finalize_kernel(float* __restrict__ out) {
    if (threadIdx.x == 0 && blockIdx.x == 0) {
        float loss = 0.0f;
        for (int n = 0; n < NSAMP; ++n) {
            const unsigned* g = &g_counts[n * 3 * NCLS];
            float ctsum = 0.0f;
            for (int c = 1; c < NCLS; ++c) ctsum += (float)g[NCLS + c];
            for (int c = 1; c < NCLS; ++c) {
                const float cp = (float)g[c];
                const float ct = (float)g[NCLS + c];
                const float I  = (float)g[2 * NCLS + c];
                const float denom = cp + ct;
                if (denom > 0.0f && ctsum > 0.0f) {
                    const float dice = 2.0f * I / denom;
                    const float w = ct / ctsum / (float)NSAMP;
                    loss += w * dice;
                }
            }
        }
        out[0] = 1.0f - loss;
    }
}

extern "C" void kernel_launch(void* const* d_in, const int* in_sizes, int n_in,
                              void* d_out, int out_size) {
    const int* yp = (const int*)d_in[0];
    const int* yt = (const int*)d_in[1];
    float* out = (float*)d_out;

    zero_counts_kernel<<<1, 128>>>();
    dim3 grid(BLOCKS_X, NSAMP);
    hist_kernel<<<grid, THREADS>>>(yp, yt);
    finalize_kernel<<<1, 32>>>(out);
}

// round 3
// speedup vs baseline: 5.9750x; 1.1242x over previous
#include <cuda_runtime.h>

#define NCLS 10
#define NSAMP 4
#define PER_SAMPLE 4096000            // 160*160*160
#define THREADS 256
#define BLOCKS_X 250                  // 250*256 threads * 64 elem = 4,096,000
#define TOTAL_BLOCKS (BLOCKS_X * NSAMP)
#define VEC_PER_SAMPLE (PER_SAMPLE/4) // 1,024,000 int4
#define STRIDE (BLOCKS_X*THREADS)     // 64,000 int4 per grid step
#define INNER 8                       // 8 int4 = 32 elements between flushes
#define OUTER 2                       // 2 * 32 = 64 elements per thread

// [sample][3][class] (0=pred,1=true,2=inter) — zero-initialized at load,
// re-zeroed by the finalizing block each run (graph-replay safe).
__device__ unsigned int g_counts[NSAMP * 3 * NCLS];
__device__ unsigned int g_ticket;

__global__ __launch_bounds__(THREADS)
void dice_fused_kernel(const int* __restrict__ yp, const int* __restrict__ yt,
                       float* __restrict__ out) {
    const int sample = blockIdx.y;
    const int4* __restrict__ p4 =
        reinterpret_cast<const int4*>(yp) + (size_t)sample * VEC_PER_SAMPLE;
    const int4* __restrict__ t4 =
        reinterpret_cast<const int4*>(yt) + (size_t)sample * VEC_PER_SAMPLE;

    const int tid = blockIdx.x * THREADS + threadIdx.x;

    int cntP[NCLS], cntT[NCLS], cntI[NCLS];
#pragma unroll
    for (int c = 0; c < NCLS; ++c) { cntP[c] = 0; cntT[c] = 0; cntI[c] = 0; }

#pragma unroll
    for (int g = 0; g < OUTER; ++g) {
        // Front-batch loads of this half for MLP
        int4 pv[INNER], tv[INNER];
#pragma unroll
        for (int it = 0; it < INNER; ++it) {
            const int idx = tid + (g * INNER + it) * STRIDE;
            pv[it] = __ldg(&p4[idx]);
            tv[it] = __ldg(&t4[idx]);
        }
        unsigned long long aP = 0ull, aT = 0ull, aI = 0ull;
#pragma unroll
        for (int it = 0; it < INNER; ++it) {
            const int pe[4] = {pv[it].x, pv[it].y, pv[it].z, pv[it].w};
            const int te[4] = {tv[it].x, tv[it].y, tv[it].z, tv[it].w};
#pragma unroll
            for (int j = 0; j < 4; ++j) {
                const unsigned long long vp = 1ull << (6 * pe[j]);
                const unsigned long long vt = 1ull << (6 * te[j]);
                aP += vp;
                aT += vt;
                if (pe[j] == te[j]) aI += vp;
            }
        }
        // Flush: each 6-bit field holds a count <= 32
#pragma unroll
        for (int c = 0; c < NCLS; ++c) {
            cntP[c] += (int)((aP >> (6 * c)) & 63ull);
            cntT[c] += (int)((aT >> (6 * c)) & 63ull);
            cntI[c] += (int)((aI >> (6 * c)) & 63ull);
        }
    }

    // Warp reduction (REDUX.SUM)
#pragma unroll
    for (int c = 0; c < NCLS; ++c) {
        cntP[c] = __reduce_add_sync(0xffffffffu, cntP[c]);
        cntT[c] = __reduce_add_sync(0xffffffffu, cntT[c]);
        cntI[c] = __reduce_add_sync(0xffffffffu, cntI[c]);
    }

    __shared__ int red[THREADS / 32][3 * NCLS];
    __shared__ bool s_last;
    const int warp = threadIdx.x >> 5;
    const int lane = threadIdx.x & 31;
    if (lane == 0) {
#pragma unroll
        for (int c = 0; c < NCLS; ++c) {
            red[warp][c]            = cntP[c];
            red[warp][NCLS + c]     = cntT[c];
            red[warp][2 * NCLS + c] = cntI[c];
        }
    }
    __syncthreads();
    if (threadIdx.x < 3 * NCLS) {
        int s = 0;
#pragma unroll
        for (int w = 0; w < THREADS / 32; ++w) s += red[w][threadIdx.x];
        atomicAdd(&g_counts[sample * 3 * NCLS + threadIdx.x], (unsigned)s);
    }
    __syncthreads();

    // Last-block-done: the final block computes the loss and resets scratch.
    if (threadIdx.x == 0) {
        __threadfence();
        const unsigned t = atomicAdd(&g_ticket, 1u);
        s_last = (t == (unsigned)(TOTAL_BLOCKS - 1));
    }
    __syncthreads();
    if (s_last && threadIdx.x == 0) {
        __threadfence();   // acquire: all other blocks' counts are visible
        float loss = 0.0f;
        for (int n = 0; n < NSAMP; ++n) {
            const unsigned* g = &g_counts[n * 3 * NCLS];
            float ctsum = 0.0f;
            for (int c = 1; c < NCLS; ++c) ctsum += (float)g[NCLS + c];
            for (int c = 1; c < NCLS; ++c) {
                const float cp = (float)g[c];
                const float ct = (float)g[NCLS + c];
                const float I  = (float)g[2 * NCLS + c];
                const float denom = cp + ct;
                if (denom > 0.0f && ctsum > 0.0f) {
                    loss += (ct / ctsum / (float)NSAMP) * (2.0f * I / denom);
                }
            }
        }
        out[0] = 1.0f - loss;
        // Reset scratch for the next graph replay
        for (int i = 0; i < NSAMP * 3 * NCLS; ++i) g_counts[i] = 0u;
        __threadfence();
        g_ticket = 0u;
    }
}

extern "C" void kernel_launch(void* const* d_in, const int* in_sizes, int n_in,
                              void* d_out, int out_size) {
    const int* yp = (const int*)d_in[0];
    const int* yt = (const int*)d_in[1];
    float* out = (float*)d_out;

    dim3 grid(BLOCKS_X, NSAMP);
    dice_fused_kernel<<<grid, THREADS>>>(yp, yt, out);
}